// round 5
// baseline (speedup 1.0000x reference)
#include <cuda_runtime.h>
#include <cstdint>

// Problem constants (fixed by reference setup_inputs).
constexpr int N_MOLS      = 2000;
constexpr int N_PER_MOL   = 64;
constexpr int PAIRS_PER_M = N_PER_MOL * (N_PER_MOL - 1);   // 4032
constexpr float CUTOFF    = 5.0f;

// Output layout (flatten of reference tuple, all float32):
//   [0,    P)  : i_idx
//   [P,   2P)  : j_idx
//   [2P,  3P)  : d_ij
//   [3P,  6P)  : r_ij (row-major [P,3])
// with P = N_MOLS * PAIRS_PER_M = 8,064,000.

__global__ __launch_bounds__(256)
void neighborlist_kernel(const float* __restrict__ pos, float* __restrict__ out)
{
    __shared__ float sx[N_PER_MOL];
    __shared__ float sy[N_PER_MOL];
    __shared__ float sz[N_PER_MOL];

    const int m = blockIdx.x;
    const int t = threadIdx.x;

    if (t < N_PER_MOL) {
        const float* p = pos + (size_t)(m * N_PER_MOL + t) * 3;
        sx[t] = p[0];
        sy[t] = p[1];
        sz[t] = p[2];
    }
    __syncthreads();

    const int warp = t >> 5;
    const int lane = t & 31;

    const size_t P = (size_t)N_MOLS * PAIRS_PER_M;
    float* __restrict__ out_i = out;
    float* __restrict__ out_j = out + P;
    float* __restrict__ out_d = out + 2 * P;
    float* __restrict__ out_r = out + 3 * P;

    const size_t base   = (size_t)m * PAIRS_PER_M;
    const float  fabase = (float)(m * N_PER_MOL);

    // Each warp owns rows i = warp, warp+8, ... (8 rows of 63 pairs each).
    for (int i = warp; i < N_PER_MOL; i += 8) {
        const float xi = sx[i];
        const float yi = sy[i];
        const float zi = sz[i];
        const float fi = fabase + (float)i;
        const size_t rowbase = base + (size_t)i * 63;

        #pragma unroll
        for (int half = 0; half < 2; half++) {
            const int jc = half * 32 + lane;
            if (jc < 63) {
                const int j = jc + (jc >= i ? 1 : 0);

                const float dx = sx[j] - xi;
                const float dy = sy[j] - yi;
                const float dz = sz[j] - zi;
                const float d  = sqrtf(fmaf(dx, dx, fmaf(dy, dy, dz * dz)));

                const bool in_cut = (d <= CUTOFF);

                const size_t g = rowbase + jc;
                out_i[g] = fi;
                out_j[g] = fabase + (float)j;
                out_d[g] = in_cut ? d : 0.0f;

                float* __restrict__ r = out_r + 3 * g;
                r[0] = in_cut ? dx : 0.0f;
                r[1] = in_cut ? dy : 0.0f;
                r[2] = in_cut ? dz : 0.0f;
            }
        }
    }
}

extern "C" void kernel_launch(void* const* d_in, const int* in_sizes, int n_in,
                              void* d_out, int out_size)
{
    const float* pos = (const float*)d_in[0];
    float* out = (float*)d_out;
    neighborlist_kernel<<<N_MOLS, 256>>>(pos, out);
}

// round 6
// speedup vs baseline: 1.3278x; 1.3278x over previous
#include <cuda_runtime.h>
#include <cstdint>

// Problem constants (fixed by reference setup_inputs).
constexpr int N_MOLS      = 2000;
constexpr int N_PER_MOL   = 64;
constexpr int PAIRS_PER_M = N_PER_MOL * (N_PER_MOL - 1);   // 4032
constexpr int HALF_PAIRS  = PAIRS_PER_M / 2;               // 2016 (2 pairs per thread)
constexpr float CUT2      = 25.0f;                         // 5.0^2

// Output layout (flatten of reference tuple, all float32):
//   [0,    P)  : i_idx
//   [P,   2P)  : j_idx
//   [2P,  3P)  : d_ij
//   [3P,  6P)  : r_ij (row-major [P,3])
// with P = N_MOLS * PAIRS_PER_M = 8,064,000.

__global__ __launch_bounds__(256)
void neighborlist_kernel(const float* __restrict__ pos, float* __restrict__ out)
{
    __shared__ float sx[N_PER_MOL];
    __shared__ float sy[N_PER_MOL];
    __shared__ float sz[N_PER_MOL];

    const int m = blockIdx.x;
    const int t = threadIdx.x;

    if (t < N_PER_MOL) {
        const float* p = pos + (unsigned)(m * N_PER_MOL + t) * 3u;
        sx[t] = p[0];
        sy[t] = p[1];
        sz[t] = p[2];
    }
    __syncthreads();

    const unsigned P = (unsigned)N_MOLS * PAIRS_PER_M;
    float* __restrict__ out_i = out;
    float* __restrict__ out_j = out + P;
    float* __restrict__ out_d = out + 2u * P;
    float* __restrict__ out_r = out + 3u * P;

    const unsigned base   = (unsigned)m * PAIRS_PER_M;
    const float    fabase = (float)(m * N_PER_MOL);

    // Each thread handles 2 consecutive pairs; chunks of 512 pairs per
    // 256-thread pass keep every warp's stores 128B-line aligned.
    for (int c = t; c < HALF_PAIRS; c += 256) {
        const int p0 = c * 2;

        // Decode pair 0
        int i0  = p0 / 63;                    // const-div -> mul/shift
        int jr0 = p0 - i0 * 63;
        const int j0 = jr0 + (jr0 >= i0 ? 1 : 0);

        // Decode pair 1 incrementally
        int jr1 = jr0 + 1;
        const int wrap = (jr1 == 63);
        const int i1 = i0 + wrap;
        jr1 = wrap ? 0 : jr1;
        const int j1 = jr1 + (jr1 >= i1 ? 1 : 0);

        // Pair 0
        const float dx0 = sx[j0] - sx[i0];
        const float dy0 = sy[j0] - sy[i0];
        const float dz0 = sz[j0] - sz[i0];
        const float q0  = fmaf(dx0, dx0, fmaf(dy0, dy0, dz0 * dz0));
        const bool  c0  = (q0 <= CUT2);
        const float d0  = c0 ? sqrtf(q0) : 0.0f;

        // Pair 1
        const float dx1 = sx[j1] - sx[i1];
        const float dy1 = sy[j1] - sy[i1];
        const float dz1 = sz[j1] - sz[i1];
        const float q1  = fmaf(dx1, dx1, fmaf(dy1, dy1, dz1 * dz1));
        const bool  c1  = (q1 <= CUT2);
        const float d1  = c1 ? sqrtf(q1) : 0.0f;

        const unsigned g = base + (unsigned)p0;        // even -> 8B aligned

        *(float2*)(out_i + g) = make_float2(fabase + (float)i0, fabase + (float)i1);
        *(float2*)(out_j + g) = make_float2(fabase + (float)j0, fabase + (float)j1);
        *(float2*)(out_d + g) = make_float2(d0, d1);

        float* __restrict__ r = out_r + 3u * g;        // 3*even -> 8B aligned
        *(float2*)(r + 0) = make_float2(c0 ? dx0 : 0.0f, c0 ? dy0 : 0.0f);
        *(float2*)(r + 2) = make_float2(c0 ? dz0 : 0.0f, c1 ? dx1 : 0.0f);
        *(float2*)(r + 4) = make_float2(c1 ? dy1 : 0.0f, c1 ? dz1 : 0.0f);
    }
}

extern "C" void kernel_launch(void* const* d_in, const int* in_sizes, int n_in,
                              void* d_out, int out_size)
{
    const float* pos = (const float*)d_in[0];
    float* out = (float*)d_out;
    neighborlist_kernel<<<N_MOLS, 256>>>(pos, out);
}